// round 1
// baseline (speedup 1.0000x reference)
#include <cuda_runtime.h>
#include <math.h>

// Problem constants (all exact divisors — no bounds checks needed)
#define BS   32768   // B*S tokens
#define NQ   8
#define FFN  2048
#define EMB  512

// Tiling
#define TM   64      // tokens per block
#define TN   128     // output cols per block
#define KC   32      // FFN chunk
#define NTHREADS 256

__global__ __launch_bounds__(NTHREADS, 2)
void ffq_fused_kernel(const float* __restrict__ x,
                      const float* __restrict__ theta,
                      const float* __restrict__ W1,
                      const float* __restrict__ b1,
                      const float* __restrict__ W2,
                      const float* __restrict__ b2,
                      float* __restrict__ out)
{
    // smem: ~28.4 KB total (fits static 48 KB limit)
    __shared__ float ct_s[NQ];
    __shared__ float q_s[TM][NQ + 1];     // pad 9 -> conflict-free strided reads
    __shared__ float w1_s[NQ][KC];        // 1 KB
    __shared__ float h_s[KC][TM + 4];     // transposed, pad 68 keeps 16B align
    __shared__ float w2_s[KC][TN];        // 16 KB

    const int tid  = threadIdx.x;
    const int row0 = blockIdx.x * TM;     // token tile
    const int col0 = blockIdx.y * TN;     // output-col tile

    // cos(theta), 8 values
    if (tid < NQ) ct_s[tid] = cosf(theta[tid]);
    __syncthreads();

    // q tile: q[m][j] = cos(x[m,j]) * cos(theta[j])
    #pragma unroll
    for (int i = tid; i < TM * NQ; i += NTHREADS) {
        int m = i / NQ, j = i % NQ;
        q_s[m][j] = cosf(x[(size_t)(row0 + m) * NQ + j]) * ct_s[j];
    }
    __syncthreads();

    // output thread tile: warp = row group (8 rows), lane = col group (4 cols)
    const int tx = tid & 31;
    const int ty = tid >> 5;
    const int c0 = tx * 4;
    const int m0 = ty * 8;

    float acc[8][4];
    #pragma unroll
    for (int i = 0; i < 8; i++)
        #pragma unroll
        for (int j = 0; j < 4; j++) acc[i][j] = 0.f;

    for (int kg = 0; kg < FFN; kg += KC) {
        // ---- phase 1: stage W1 chunk [NQ][KC] and W2 chunk [KC][TN] ----
        {
            // 8*32 = 256 elems, one per thread, coalesced per warp
            int j = tid >> 5, k = tid & 31;
            w1_s[j][k] = W1[(size_t)j * FFN + kg + k];

            const float4* w2g = (const float4*)(W2 + (size_t)kg * EMB + col0);
            #pragma unroll
            for (int i = 0; i < (KC * TN / 4) / NTHREADS; i++) {   // 4
                int e   = tid + i * NTHREADS;
                int kk  = e >> 5;          // TN/4 = 32 float4 per row
                int c4  = e & 31;
                ((float4*)w2_s)[kk * (TN / 4) + c4] = w2g[(size_t)kk * (EMB / 4) + c4];
            }
        }
        __syncthreads();   // also guards h_s/w2_s reuse from previous chunk

        // ---- phase 2: h chunk = relu(q @ W1chunk + b1), stored transposed ----
        #pragma unroll
        for (int i = 0; i < (TM * KC) / NTHREADS; i++) {           // 8
            int e = tid + i * NTHREADS;
            int m = e & (TM - 1);          // consecutive lanes -> consecutive m
            int k = e >> 6;                // lane-uniform k -> broadcast LDS, bcast b1
            float s = b1[kg + k];
            #pragma unroll
            for (int j = 0; j < NQ; j++)
                s = fmaf(q_s[m][j], w1_s[j][k], s);
            h_s[k][m] = fmaxf(s, 0.f);     // conflict-free STS (consecutive m)
        }
        __syncthreads();

        // ---- phase 3: accumulate out tile ----
        #pragma unroll 8
        for (int k = 0; k < KC; k++) {
            float4 hA = *(const float4*)&h_s[k][m0];       // warp-broadcast
            float4 hB = *(const float4*)&h_s[k][m0 + 4];   // warp-broadcast
            float4 wv = *(const float4*)&w2_s[k][c0];      // conflict-free
            float hv[8] = {hA.x, hA.y, hA.z, hA.w, hB.x, hB.y, hB.z, hB.w};
            float wa[4] = {wv.x, wv.y, wv.z, wv.w};
            #pragma unroll
            for (int i = 0; i < 8; i++)
                #pragma unroll
                for (int j = 0; j < 4; j++)
                    acc[i][j] = fmaf(hv[i], wa[j], acc[i][j]);
        }
        __syncthreads();
    }

    // ---- epilogue: + b2, coalesced float4 stores ----
    float4 bv = *(const float4*)&b2[col0 + c0];
    #pragma unroll
    for (int i = 0; i < 8; i++) {
        size_t m = (size_t)(row0 + m0 + i);
        float4 o;
        o.x = acc[i][0] + bv.x;
        o.y = acc[i][1] + bv.y;
        o.z = acc[i][2] + bv.z;
        o.w = acc[i][3] + bv.w;
        *(float4*)&out[m * EMB + col0 + c0] = o;
    }
}

extern "C" void kernel_launch(void* const* d_in, const int* in_sizes, int n_in,
                              void* d_out, int out_size)
{
    // Identify inputs robustly by element count (all counts are distinct)
    const float *x = 0, *theta = 0, *W1 = 0, *b1 = 0, *W2 = 0, *b2 = 0;
    for (int i = 0; i < n_in; i++) {
        switch (in_sizes[i]) {
            case BS * NQ:    x     = (const float*)d_in[i]; break;  // 262144
            case NQ:         theta = (const float*)d_in[i]; break;  // 8
            case NQ * FFN:   W1    = (const float*)d_in[i]; break;  // 16384
            case FFN:        b1    = (const float*)d_in[i]; break;  // 2048
            case FFN * EMB:  W2    = (const float*)d_in[i]; break;  // 1048576
            case EMB:        b2    = (const float*)d_in[i]; break;  // 512
            default: break;
        }
    }

    dim3 grid(BS / TM, EMB / TN);   // 512 x 4 = 2048 blocks
    ffq_fused_kernel<<<grid, NTHREADS>>>(x, theta, W1, b1, W2, b2, (float*)d_out);
}

// round 3
// speedup vs baseline: 2.3439x; 2.3439x over previous
#include <cuda_runtime.h>
#include <cuda_bf16.h>
#include <cstdint>
#include <math.h>

#define BS   32768
#define NQ   8
#define FFN  2048
#define EMB  512

#define TMT  128              // tokens per CTA
#define TNT  128              // out cols per CTA
#define KC   16               // FFN chunk per mma K
#define NC   (FFN / KC)       // 128 chunks
#define NTH  256

// W2 transposed + bf16 hi/lo split: [EMB][FFN]
__device__ __nv_bfloat16 g_w2t_hi[EMB * FFN];
__device__ __nv_bfloat16 g_w2t_lo[EMB * FFN];

// ---- smem layout (byte offsets in dynamic smem). Rows padded to 48B so
// ldmatrix 8-row phases hit 8 distinct 16B banks groups (conflict-free). ----
#define ROWB 48
#define SM_HHI(b) ((b) * 6144)             // 128 rows * 48B
#define SM_HLO(b) (12288 + (b) * 6144)
#define SM_WHI(b) (24576 + (b) * 6144)
#define SM_WLO(b) (36864 + (b) * 6144)
#define SM_W1(b)  (49152 + (b) * 512)      // [16][8] floats
#define SM_B1(b)  (50176 + (b) * 64)       // 16 floats
#define SMEM_BYTES 50304

__device__ __forceinline__ uint32_t smem_u32(const void* p) {
    uint32_t a;
    asm("{ .reg .u64 t; cvta.to.shared.u64 t, %1; cvt.u32.u64 %0, t; }" : "=r"(a) : "l"(p));
    return a;
}

#define LDSM4(r, a)                                                            \
    asm volatile("ldmatrix.sync.aligned.m8n8.x4.shared.b16 {%0,%1,%2,%3}, [%4];" \
        : "=r"((r)[0]), "=r"((r)[1]), "=r"((r)[2]), "=r"((r)[3]) : "r"(a))

#define MMA16816(d, a, b0, b1v)                                                \
    asm volatile("mma.sync.aligned.m16n8k16.row.col.f32.bf16.bf16.f32 "       \
        "{%0,%1,%2,%3},{%4,%5,%6,%7},{%8,%9},{%0,%1,%2,%3};"                  \
        : "+f"((d)[0]), "+f"((d)[1]), "+f"((d)[2]), "+f"((d)[3])              \
        : "r"((a)[0]), "r"((a)[1]), "r"((a)[2]), "r"((a)[3]), "r"(b0), "r"(b1v))

#define CP16(dst, src)                                                         \
    asm volatile("cp.async.cg.shared.global [%0], [%1], 16;" :: "r"(dst), "l"(src))
#define CP_COMMIT() asm volatile("cp.async.commit_group;" ::: "memory")
#define CP_WAIT0()  asm volatile("cp.async.wait_group 0;" ::: "memory")

// ---- prep: W2 [FFN][EMB] fp32 -> bf16 hi/lo transposed [EMB][FFN] ----------
__global__ void prep_w2_kernel(const float* __restrict__ W2) {
    int t = blockIdx.x * blockDim.x + threadIdx.x;
    if (t >= EMB * FFN) return;
    int n = t >> 11;                 // / FFN
    int k = t & (FFN - 1);
    float v = W2[(size_t)k * EMB + n];
    __nv_bfloat16 h = __float2bfloat16(v);
    g_w2t_hi[t] = h;
    g_w2t_lo[t] = __float2bfloat16(v - __bfloat162float(h));
}

// ---- main fused kernel ------------------------------------------------------
__global__ __launch_bounds__(NTH, 2)
void ffq_mma_kernel(const float* __restrict__ x,
                    const float* __restrict__ theta,
                    const float* __restrict__ W1,
                    const float* __restrict__ b1g,
                    const float* __restrict__ b2,
                    float* __restrict__ out)
{
    extern __shared__ char sm[];
    const uint32_t smb = smem_u32(sm);

    const int tid  = threadIdx.x;
    const int wid  = tid >> 5;
    const int lane = tid & 31;
    const int row0 = blockIdx.x * TMT;
    const int col0 = blockIdx.y * TNT;
    const int wm   = wid & 3;        // M group (32 rows)
    const int wn   = wid >> 2;       // N group (64 cols)

    // ---- per-thread q row (held in regs for the whole K loop) ----
    const int qm = tid >> 1;         // token row 0..127
    const int kh = tid & 1;          // which k-half of the 16-chunk
    float q[NQ];
    {
        const float* xr = x + (size_t)(row0 + qm) * NQ;
        #pragma unroll
        for (int j = 0; j < NQ; j++)
            q[j] = cosf(xr[j]) * cosf(__ldg(&theta[j]));
    }

    // ---- ldmatrix lane addresses (within a buffer) ----
    // A (h): tiles (m0-7,k0),(m8-15,k0),(m0-7,k8),(m8-15,k8)
    const uint32_t a_off = (uint32_t)(wm * 32 + (lane & 15)) * ROWB + ((lane >> 4) << 4);
    // B (w2t rows = n): tiles (n0-7,k0),(n0-7,k8),(n8-15,k0),(n8-15,k8)
    const uint32_t b_off = (uint32_t)(wn * 64 + (lane & 7) + ((lane & 16) >> 1)) * ROWB
                         + ((lane & 8) << 1);

    float acc[2][8][4];
    #pragma unroll
    for (int a = 0; a < 2; a++)
        #pragma unroll
        for (int b = 0; b < 8; b++)
            #pragma unroll
            for (int i = 0; i < 4; i++) acc[a][b][i] = 0.f;

    // ---- stage W1/b1 for chunks 0 and 1 ----
    if (tid < 128) {
        int k = tid >> 3, j = tid & 7;                 // w1t[k][j]
        ((float*)(sm + SM_W1(0)))[tid] = W1[(size_t)j * FFN + k];
        ((float*)(sm + SM_W1(1)))[tid] = W1[(size_t)j * FFN + KC + k];
    }
    if (tid < KC) {
        ((float*)(sm + SM_B1(0)))[tid] = b1g[tid];
        ((float*)(sm + SM_B1(1)))[tid] = b1g[KC + tid];
    }
    __syncthreads();

    // ---- producer lambda: compute h chunk + cp.async W2 chunk into buf ----
    auto produce = [&](int chunk, int buf) {
        const float* w1c = (const float*)(sm + SM_W1(chunk & 1));
        const float* b1c = (const float*)(sm + SM_B1(chunk & 1));
        uint32_t hh[4], hl[4];
        #pragma unroll
        for (int u = 0; u < 8; u++) {
            int k = kh * 8 + u;
            float4 wa = *(const float4*)&w1c[k * 8];
            float4 wb = *(const float4*)&w1c[k * 8 + 4];
            float s = b1c[k];
            s = fmaf(q[0], wa.x, s); s = fmaf(q[1], wa.y, s);
            s = fmaf(q[2], wa.z, s); s = fmaf(q[3], wa.w, s);
            s = fmaf(q[4], wb.x, s); s = fmaf(q[5], wb.y, s);
            s = fmaf(q[6], wb.z, s); s = fmaf(q[7], wb.w, s);
            s = fmaxf(s, 0.f);
            __nv_bfloat16 bh = __float2bfloat16(s);
            float rem = s - __bfloat162float(bh);
            __nv_bfloat16 bl = __float2bfloat16(rem);
            uint32_t uh = (uint32_t)__bfloat16_as_ushort(bh);
            uint32_t ul = (uint32_t)__bfloat16_as_ushort(bl);
            if (u & 1) { hh[u >> 1] |= uh << 16; hl[u >> 1] |= ul << 16; }
            else       { hh[u >> 1]  = uh;       hl[u >> 1]  = ul;       }
        }
        uint32_t ho = (uint32_t)qm * ROWB + (kh << 4);
        *(uint4*)(sm + SM_HHI(buf) + ho) = make_uint4(hh[0], hh[1], hh[2], hh[3]);
        *(uint4*)(sm + SM_HLO(buf) + ho) = make_uint4(hl[0], hl[1], hl[2], hl[3]);

        // W2 tiles via cp.async: thread covers (n = tid>>1, k-half = kh)
        size_t gofs = (size_t)(col0 + (tid >> 1)) * FFN + chunk * KC + kh * 8;
        uint32_t wo = (uint32_t)(tid >> 1) * ROWB + (kh << 4);
        CP16(smb + SM_WHI(buf) + wo, (const char*)(g_w2t_hi + gofs));
        CP16(smb + SM_WLO(buf) + wo, (const char*)(g_w2t_lo + gofs));
    };

    // prologue: fill buffer 0 with chunk 0
    produce(0, 0);
    CP_COMMIT(); CP_WAIT0();
    __syncthreads();

    for (int c = 0; c < NC; c++) {
        const int p = c & 1;

        // stage W1/b1 for chunk c+2 (read next iter by produce(c+2))
        if (c + 2 < NC) {
            if (tid < 128) {
                int k = tid >> 3, j = tid & 7;
                ((float*)(sm + SM_W1(p)))[tid] = W1[(size_t)j * FFN + (c + 2) * KC + k];
            }
            if (tid < KC)
                ((float*)(sm + SM_B1(p)))[tid] = b1g[(c + 2) * KC + tid];
        }

        // produce chunk c+1 into the other buffer
        if (c + 1 < NC) produce(c + 1, p ^ 1);

        // consume buffer p: ldmatrix + 48 mmas
        uint32_t ah[2][4], al[2][4];
        {
            uint32_t Ah = smb + SM_HHI(p) + a_off;
            uint32_t Al = smb + SM_HLO(p) + a_off;
            LDSM4(ah[0], Ah); LDSM4(ah[1], Ah + 16 * ROWB);
            LDSM4(al[0], Al); LDSM4(al[1], Al + 16 * ROWB);
        }
        #pragma unroll
        for (int g = 0; g < 4; g++) {
            uint32_t bh[4], bl[4];
            LDSM4(bh, smb + SM_WHI(p) + b_off + g * 16 * ROWB);
            LDSM4(bl, smb + SM_WLO(p) + b_off + g * 16 * ROWB);
            #pragma unroll
            for (int mt = 0; mt < 2; mt++) {
                MMA16816(acc[mt][2 * g],     ah[mt], bh[0], bh[1]);   // hi*hi
                MMA16816(acc[mt][2 * g + 1], ah[mt], bh[2], bh[3]);
                MMA16816(acc[mt][2 * g],     ah[mt], bl[0], bl[1]);   // hi*lo
                MMA16816(acc[mt][2 * g + 1], ah[mt], bl[2], bl[3]);
                MMA16816(acc[mt][2 * g],     al[mt], bh[0], bh[1]);   // lo*hi
                MMA16816(acc[mt][2 * g + 1], al[mt], bh[2], bh[3]);
            }
        }

        CP_COMMIT(); CP_WAIT0();
        __syncthreads();
    }

    // ---- epilogue: D frags + b2 -> gmem (sector-aligned float2) ----
    #pragma unroll
    for (int mt = 0; mt < 2; mt++) {
        int mrow = row0 + wm * 32 + mt * 16 + (lane >> 2);
        #pragma unroll
        for (int nt = 0; nt < 8; nt++) {
            int ncol = col0 + wn * 64 + nt * 8 + (lane & 3) * 2;
            float bx = b2[ncol], by = b2[ncol + 1];
            float2 v0 = make_float2(acc[mt][nt][0] + bx, acc[mt][nt][1] + by);
            float2 v1 = make_float2(acc[mt][nt][2] + bx, acc[mt][nt][3] + by);
            *(float2*)&out[(size_t)mrow * EMB + ncol]       = v0;
            *(float2*)&out[(size_t)(mrow + 8) * EMB + ncol] = v1;
        }
    }
}

// ---- launcher ----------------------------------------------------------------
extern "C" void kernel_launch(void* const* d_in, const int* in_sizes, int n_in,
                              void* d_out, int out_size)
{
    const float *x = 0, *theta = 0, *W1 = 0, *b1 = 0, *W2 = 0, *b2 = 0;
    for (int i = 0; i < n_in; i++) {
        switch (in_sizes[i]) {
            case BS * NQ:   x     = (const float*)d_in[i]; break;
            case NQ:        theta = (const float*)d_in[i]; break;
            case NQ * FFN:  W1    = (const float*)d_in[i]; break;
            case FFN:       b1    = (const float*)d_in[i]; break;
            case FFN * EMB: W2    = (const float*)d_in[i]; break;
            case EMB:       b2    = (const float*)d_in[i]; break;
            default: break;
        }
    }

    prep_w2_kernel<<<(EMB * FFN + 255) / 256, 256>>>(W2);

    cudaFuncSetAttribute(ffq_mma_kernel, cudaFuncAttributeMaxDynamicSharedMemorySize,
                         SMEM_BYTES);
    dim3 grid(BS / TMT, EMB / TNT);   // 256 x 4 = 1024 CTAs
    ffq_mma_kernel<<<grid, NTH, SMEM_BYTES>>>(x, theta, W1, b1, b2, (float*)d_out);
}